// round 12
// baseline (speedup 1.0000x reference)
#include <cuda_runtime.h>
#include <cuda_bf16.h>
#include <cstdint>

// Problem constants
#define T_ 64
#define B_ 16
#define DIM_ 512
#define H_ 8
#define DH_ 64
#define ETA_ 4
#define FD_ 256           // ETA_*DH_
#define NPROJ 2656        // 5*512 + 3*32
#define NPROJ_PAD 2688
#define MROWS 1024        // T_*B_
#define NBH 128           // B_*H_

// Output layout: output[T,B,DIM], kv_last[B,H,FD,Dh], nm_last[B,H,FD]
#define OUT_OFF_KV  (T_*B_*DIM_)
#define OUT_OFF_NM  (OUT_OFF_KV + B_*H_*FD_*DH_)

// Scratch (device globals — no allocation allowed)
__device__ float g_proj[MROWS * NPROJ_PAD];      // ~11 MB
__device__ float g_attn[MROWS * (H_*DH_)];       // 2 MB
__device__ float g_sc[T_ * NBH * 768];           // 25 MB: disc|gk|phi per (t,bh)
__device__ float g_gv[T_ * NBH * DH_];           // 2 MB
__device__ float g_phinm[T_ * NBH * FD_];        // 8 MB
__device__ float g_den[T_ * NBH];                // 32 KB

// ---------------------------------------------------------------------------
// f32x2 packed helpers
// ---------------------------------------------------------------------------
__device__ __forceinline__ unsigned long long pk2(float lo, float hi) {
    unsigned long long r;
    asm("mov.b64 %0, {%1, %2};" : "=l"(r) : "f"(lo), "f"(hi));
    return r;
}
__device__ __forceinline__ void unpk2(float& lo, float& hi, unsigned long long v) {
    asm("mov.b64 {%0, %1}, %2;" : "=f"(lo), "=f"(hi) : "l"(v));
}
__device__ __forceinline__ unsigned long long fma2_(unsigned long long a,
                                                    unsigned long long b,
                                                    unsigned long long c) {
    unsigned long long d;
    asm("fma.rn.f32x2 %0, %1, %2, %3;" : "=l"(d) : "l"(a), "l"(b), "l"(c));
    return d;
}
__device__ __forceinline__ unsigned long long mul2_(unsigned long long a,
                                                    unsigned long long b) {
    unsigned long long d;
    asm("mul.rn.f32x2 %0, %1, %2;" : "=l"(d) : "l"(a), "l"(b));
    return d;
}

__device__ __forceinline__ float sigmoidf_(float x) {
    return 1.f / (1.f + __expf(-x));
}

// ---------------------------------------------------------------------------
// GEMM 1: projections (measured config: 64x64x16, 4x4 micro, 256 thr)
// ---------------------------------------------------------------------------
#define BM 64
#define BN 64
#define BK 16

__global__ __launch_bounds__(256)
void proj_gemm(const float* __restrict__ X,
               const float* __restrict__ Wq, const float* __restrict__ Wk,
               const float* __restrict__ Wv, const float* __restrict__ Wb,
               const float* __restrict__ Wg, const float* __restrict__ Wp1,
               const float* __restrict__ Wp2, const float* __restrict__ Wp3)
{
    __shared__ float Xs[BK][BM + 4];
    __shared__ float Ws[BK][BN + 4];

    const int tid = threadIdx.x;
    const int m0 = blockIdx.y * BM;
    const int n0 = blockIdx.x * BN;

    const int lr = tid >> 2;
    const int lc = (tid & 3) * 4;
    const int tx = tid & 15;
    const int ty = tid >> 4;

    const int n = n0 + lr;
    const float* wrow = nullptr;
    if (n < 2560) {
        const int wi = n >> 9;
        const int nl = n & 511;
        const float* wb = (wi == 0) ? Wq : (wi == 1) ? Wk : (wi == 2) ? Wv
                         : (wi == 3) ? Wb : Wg;
        wrow = wb + nl * DIM_;
    } else if (n < NPROJ) {
        const int nn = n - 2560;
        const int wi = nn >> 5;
        const int nl = nn & 31;
        const float* wb = (wi == 0) ? Wp1 : (wi == 1) ? Wp2 : Wp3;
        wrow = wb + nl * DIM_;
    }
    const float* xrow = X + (size_t)(m0 + lr) * DIM_;

    float acc[4][4];
#pragma unroll
    for (int i = 0; i < 4; i++)
#pragma unroll
        for (int j = 0; j < 4; j++) acc[i][j] = 0.f;

    for (int k0 = 0; k0 < DIM_; k0 += BK) {
        float4 xv = *(const float4*)(xrow + k0 + lc);
        float4 wv = make_float4(0.f, 0.f, 0.f, 0.f);
        if (wrow) wv = *(const float4*)(wrow + k0 + lc);
        Xs[lc + 0][lr] = xv.x; Xs[lc + 1][lr] = xv.y;
        Xs[lc + 2][lr] = xv.z; Xs[lc + 3][lr] = xv.w;
        Ws[lc + 0][lr] = wv.x; Ws[lc + 1][lr] = wv.y;
        Ws[lc + 2][lr] = wv.z; Ws[lc + 3][lr] = wv.w;
        __syncthreads();
#pragma unroll
        for (int kk = 0; kk < BK; kk++) {
            float4 a = *(const float4*)&Xs[kk][ty * 4];
            float4 bq = *(const float4*)&Ws[kk][tx * 4];
            float av[4] = {a.x, a.y, a.z, a.w};
            float bv[4] = {bq.x, bq.y, bq.z, bq.w};
#pragma unroll
            for (int i = 0; i < 4; i++)
#pragma unroll
                for (int j = 0; j < 4; j++) acc[i][j] += av[i] * bv[j];
        }
        __syncthreads();
    }

#pragma unroll
    for (int i = 0; i < 4; i++) {
        const int m = m0 + ty * 4 + i;
#pragma unroll
        for (int j = 0; j < 4; j++) {
            g_proj[(size_t)m * NPROJ_PAD + n0 + tx * 4 + j] = acc[i][j];
        }
    }
}

// ---------------------------------------------------------------------------
// Scan A: per-(bh,FD) nm recurrence + all per-step scalars. NO barriers.
// ---------------------------------------------------------------------------
__global__ __launch_bounds__(256)
void scan_a(const int* __restrict__ term,
            const float* __restrict__ nm_prev,
            float* __restrict__ nm_out)
{
    const int bh = blockIdx.x;   // 0..127
    const int b  = bh >> 3;
    const int h  = bh & 7;
    const int tid = threadIdx.x; // FD index
    const int e  = tid >> 6;
    const int dd = tid & 63;
    const int hcol = h * DH_;
    const int pofs = h * ETA_ + e;

    float nm = nm_prev[bh * FD_ + tid];

    float r_q, r_k, r_g, r_p1, r_p2, r_p3, r_v, r_b;
    int r_t;
    {
        const float* P = g_proj + (size_t)b * NPROJ_PAD;
        r_q  = P[hcol + dd];
        r_k  = P[512 + hcol + dd];
        r_g  = P[2048 + hcol + dd];
        r_p1 = P[2560 + pofs];
        r_p2 = P[2592 + pofs];
        r_p3 = P[2624 + pofs];
        r_t  = term[b];
        if (tid < 64) {
            r_v = P[1024 + hcol + tid];
            r_b = P[1536 + hcol + tid];
        }
    }

    for (int t = 0; t < T_; t++) {
        const float sgamma = sigmoidf_(r_g);
        const float gf   = sigmoidf_(r_p3) * sgamma;
        const float mask = r_t ? 0.f : 1.f;
        const float disc = (1.f - gf) * mask;
        const float gkv  = fmaxf(r_p1, 0.f) * r_k * gf;
        const float phi  = fmaxf(r_p2, 0.f) * r_q;
        float gv = 0.f;
        if (tid < 64) gv = r_v * sigmoidf_(r_b);

        // prefetch t+1
        if (t + 1 < T_) {
            const float* Pn = g_proj + (size_t)((t + 1) * B_ + b) * NPROJ_PAD;
            r_q  = Pn[hcol + dd];
            r_k  = Pn[512 + hcol + dd];
            r_g  = Pn[2048 + hcol + dd];
            r_p1 = Pn[2560 + pofs];
            r_p2 = Pn[2592 + pofs];
            r_p3 = Pn[2624 + pofs];
            r_t  = term[(t + 1) * B_ + b];
            if (tid < 64) {
                r_v = Pn[1024 + hcol + tid];
                r_b = Pn[1536 + hcol + tid];
            }
        }

        nm = fmaf(disc, nm, gkv);

        const size_t sb = (size_t)(t * NBH + bh);
        g_sc[sb * 768 + tid]       = disc;
        g_sc[sb * 768 + 256 + tid] = gkv;
        g_sc[sb * 768 + 512 + tid] = phi;
        g_phinm[sb * FD_ + tid]    = phi * nm;
        if (tid < 64) g_gv[sb * DH_ + tid] = gv;
    }

    nm_out[bh * FD_ + tid] = nm;
}

// ---------------------------------------------------------------------------
// Scan den: den[t,bh] = sum_FD phinm.  One warp per (t,bh); parallel over t.
// ---------------------------------------------------------------------------
__global__ __launch_bounds__(256)
void scan_den()
{
    const int gidx = blockIdx.x * 8 + (threadIdx.x >> 5);  // 0..8191
    const int l = threadIdx.x & 31;
    const float4* p = (const float4*)(g_phinm + (size_t)gidx * FD_);
    float4 v0 = p[l * 2];
    float4 v1 = p[l * 2 + 1];
    float s = ((v0.x + v0.y) + (v0.z + v0.w)) + ((v1.x + v1.y) + (v1.z + v1.w));
#pragma unroll
    for (int o = 16; o; o >>= 1)
        s += __shfl_xor_sync(0xFFFFFFFFu, s, o);
    if (l == 0) g_den[gidx] = s;
}

// ---------------------------------------------------------------------------
// Scan B: pure kv recurrence. 2 blocks per bh (d-halves), 256 threads.
//   warp w covers d = ds*32 + w*4 + (lane&3); fg = lane>>2 (8 FD groups).
//   Per step: double-buffered smem stage, 1 barrier, packed f32x2 update,
//   num reduced by 3 shfl-bfly (over fg lanes), den precomputed.
//   Smem scalar layout padded: [arr][fg*36 + j] → 144B fg-stride, no conflicts.
// ---------------------------------------------------------------------------
__global__ __launch_bounds__(256)
void scan_b(const float* __restrict__ kv_prev,
            float* __restrict__ kv_out)
{
    const int blk = blockIdx.x;   // 0..255
    const int bh  = blk >> 1;
    const int ds  = blk & 1;
    const int b   = bh >> 3;
    const int h   = bh & 7;
    const int tid = threadIdx.x;
    const int w   = tid >> 5;
    const int l   = tid & 31;
    const int fg  = l >> 2;       // FD group (32 rows)
    const int dlow = l & 3;
    const int dloc = w * 4 + dlow; // 0..31
    const int d   = ds * 32 + dloc;
    const int hcol = h * DH_;

    // padded smem: 3 arrays x 8 fg-rows x 36 floats, double buffered
    __shared__ float s_sc[2][3 * 8 * 36];    // 864 floats per buf
    __shared__ float s_gv[2][32];

    // kv state: FD rows [fg*32, fg*32+32) for column d, packed pairs
    unsigned long long kv2[16];
    {
        const float* kvp = kv_prev + (size_t)bh * FD_ * DH_;
#pragma unroll
        for (int p = 0; p < 16; p++) {
            const float lo = kvp[(fg * 32 + 2*p    ) * DH_ + d];
            const float hi = kvp[(fg * 32 + 2*p + 1) * DH_ + d];
            kv2[p] = pk2(lo, hi);
        }
    }

    // staging map: thread tid handles element (arr i, chunk tid>>5, j tid&31)
    const int sfg = tid >> 5;
    const int sj  = tid & 31;

    // stage t = 0
    {
        const size_t sb = (size_t)bh * 768;
#pragma unroll
        for (int i = 0; i < 3; i++)
            s_sc[0][i * 288 + sfg * 36 + sj] = g_sc[sb + i * 256 + tid];
        if (tid < 32) s_gv[0][tid] = g_gv[(size_t)bh * DH_ + ds * 32 + tid];
    }
    float rden = g_den[bh];
    __syncthreads();

    for (int t = 0; t < T_; t++) {
        const int buf = t & 1;

        // prefetch t+1 into regs
        float f0, f1, f2, fgv, rden_n;
        if (t + 1 < T_) {
            const size_t sb = (size_t)((t + 1) * NBH + bh) * 768;
            f0 = g_sc[sb + tid];
            f1 = g_sc[sb + 256 + tid];
            f2 = g_sc[sb + 512 + tid];
            if (tid < 32)
                fgv = g_gv[(size_t)((t + 1) * NBH + bh) * DH_ + ds * 32 + tid];
            rden_n = g_den[(t + 1) * NBH + bh];
        }

        // packed kv recurrence + num contraction
        const float gvd = s_gv[buf][dloc];
        const unsigned long long gvd2 = pk2(gvd, gvd);
        const ulonglong2* D2 = (const ulonglong2*)&s_sc[buf][          fg * 36];
        const ulonglong2* G2 = (const ulonglong2*)&s_sc[buf][288     + fg * 36];
        const ulonglong2* P2 = (const ulonglong2*)&s_sc[buf][2 * 288 + fg * 36];
        unsigned long long np01 = 0ULL, np23 = 0ULL;
#pragma unroll
        for (int jq = 0; jq < 8; jq++) {
            const ulonglong2 D = D2[jq];
            const ulonglong2 G = G2[jq];
            const ulonglong2 Ph = P2[jq];
            kv2[2*jq]     = fma2_(D.x, kv2[2*jq],     mul2_(gvd2, G.x));
            kv2[2*jq + 1] = fma2_(D.y, kv2[2*jq + 1], mul2_(gvd2, G.y));
            np01 = fma2_(kv2[2*jq],     Ph.x, np01);
            np23 = fma2_(kv2[2*jq + 1], Ph.y, np23);
        }
        float a0, a1, a2, a3;
        unpk2(a0, a1, np01);
        unpk2(a2, a3, np23);
        float np = (a0 + a1) + (a2 + a3);

        // reduce over the 8 fg groups (lane bits 2..4)
        np += __shfl_xor_sync(0xFFFFFFFFu, np, 4);
        np += __shfl_xor_sync(0xFFFFFFFFu, np, 8);
        np += __shfl_xor_sync(0xFFFFFFFFu, np, 16);

        if (l < 4) {
            const int row = t * B_ + b;
            g_attn[(size_t)row * (H_*DH_) + hcol + d] = np / (rden + 1e-6f);
        }

        // store staged data for t+1
        if (t + 1 < T_) {
            const int nb = buf ^ 1;
            s_sc[nb][          sfg * 36 + sj] = f0;
            s_sc[nb][288     + sfg * 36 + sj] = f1;
            s_sc[nb][2 * 288 + sfg * 36 + sj] = f2;
            if (tid < 32) s_gv[nb][tid] = fgv;
            rden = rden_n;
        }
        __syncthreads();
    }

    // write final kv state
    float* kvo = kv_out + (size_t)bh * FD_ * DH_;
#pragma unroll
    for (int p = 0; p < 16; p++) {
        float lo, hi;
        unpk2(lo, hi, kv2[p]);
        kvo[(fg * 32 + 2*p    ) * DH_ + d] = lo;
        kvo[(fg * 32 + 2*p + 1) * DH_ + d] = hi;
    }
}

// ---------------------------------------------------------------------------
// GEMM 2: direct output GEMM with fused bias.
// ---------------------------------------------------------------------------
__global__ __launch_bounds__(256)
void out_gemm(const float* __restrict__ Wo, const float* __restrict__ bo,
              float* __restrict__ out)
{
    __shared__ float Xs[BK][BM + 4];
    __shared__ float Ws[BK][BN + 4];

    const int tid = threadIdx.x;
    const int m0 = blockIdx.y * BM;
    const int n0 = blockIdx.x * BN;

    const int lr = tid >> 2;
    const int lc = (tid & 3) * 4;
    const int tx = tid & 15;
    const int ty = tid >> 4;

    const float* xrow = g_attn + (size_t)(m0 + lr) * DIM_;
    const float* wrow = Wo + (size_t)(n0 + lr) * DIM_;

    float acc[4][4];
#pragma unroll
    for (int i = 0; i < 4; i++)
#pragma unroll
        for (int j = 0; j < 4; j++) acc[i][j] = 0.f;

    for (int k0 = 0; k0 < DIM_; k0 += BK) {
        float4 xv = *(const float4*)(xrow + k0 + lc);
        float4 wv = *(const float4*)(wrow + k0 + lc);
        Xs[lc + 0][lr] = xv.x; Xs[lc + 1][lr] = xv.y;
        Xs[lc + 2][lr] = xv.z; Xs[lc + 3][lr] = xv.w;
        Ws[lc + 0][lr] = wv.x; Ws[lc + 1][lr] = wv.y;
        Ws[lc + 2][lr] = wv.z; Ws[lc + 3][lr] = wv.w;
        __syncthreads();
#pragma unroll
        for (int kk = 0; kk < BK; kk++) {
            float4 a = *(const float4*)&Xs[kk][ty * 4];
            float4 bq = *(const float4*)&Ws[kk][tx * 4];
            float av[4] = {a.x, a.y, a.z, a.w};
            float bv[4] = {bq.x, bq.y, bq.z, bq.w};
#pragma unroll
            for (int i = 0; i < 4; i++)
#pragma unroll
                for (int j = 0; j < 4; j++)
                    acc[i][j] = fmaf(av[i], bv[j], acc[i][j]);
        }
        __syncthreads();
    }

#pragma unroll
    for (int i = 0; i < 4; i++) {
        const int m = m0 + ty * 4 + i;
#pragma unroll
        for (int j = 0; j < 4; j++) {
            const int nn = n0 + tx * 4 + j;
            out[(size_t)m * DIM_ + nn] = acc[i][j] + bo[nn];
        }
    }
}

// ---------------------------------------------------------------------------
// Launch
// ---------------------------------------------------------------------------
extern "C" void kernel_launch(void* const* d_in, const int* in_sizes, int n_in,
                              void* d_out, int out_size)
{
    const float* X    = (const float*)d_in[0];
    const int*   term = (const int*)d_in[1];
    const float* kvp  = (const float*)d_in[2];
    const float* nmp  = (const float*)d_in[3];
    const float* Wq   = (const float*)d_in[4];
    const float* Wk   = (const float*)d_in[5];
    const float* Wv   = (const float*)d_in[6];
    const float* Wb   = (const float*)d_in[7];
    const float* Wg   = (const float*)d_in[8];
    const float* Wp1  = (const float*)d_in[9];
    const float* Wp2  = (const float*)d_in[10];
    const float* Wp3  = (const float*)d_in[11];
    const float* Wo   = (const float*)d_in[12];
    const float* bo   = (const float*)d_in[13];
    float* out = (float*)d_out;

    dim3 gp(NPROJ_PAD / BN, MROWS / BM);       // 42 x 16 = 672 blocks
    proj_gemm<<<gp, 256>>>(X, Wq, Wk, Wv, Wb, Wg, Wp1, Wp2, Wp3);

    scan_a<<<NBH, 256>>>(term, nmp, out + OUT_OFF_NM);

    scan_den<<<(T_ * NBH) / 8, 256>>>();       // 1024 blocks, 1 warp/(t,bh)

    scan_b<<<NBH * 2, 256>>>(kvp, out + OUT_OFF_KV);

    dim3 go(DIM_ / BN, MROWS / BM);            // 8 x 16 = 128 blocks
    out_gemm<<<go, 256>>>(Wo, bo, out);
}

// round 13
// speedup vs baseline: 1.2263x; 1.2263x over previous
#include <cuda_runtime.h>
#include <cuda_bf16.h>
#include <cstdint>

// Problem constants
#define T_ 64
#define B_ 16
#define DIM_ 512
#define H_ 8
#define DH_ 64
#define ETA_ 4
#define FD_ 256           // ETA_*DH_
#define NPROJ 2656        // 5*512 + 3*32
#define NPROJ_PAD 2688
#define MROWS 1024        // T_*B_

// Output layout: output[T,B,DIM], kv_last[B,H,FD,Dh], nm_last[B,H,FD]
#define OUT_OFF_KV  (T_*B_*DIM_)
#define OUT_OFF_NM  (OUT_OFF_KV + B_*H_*FD_*DH_)

// Scratch (device globals — no allocation allowed)
__device__ float g_proj[MROWS * NPROJ_PAD];
__device__ float g_attn[MROWS * (H_*DH_)];

// ---------------------------------------------------------------------------
// f32x2 packed helpers
// ---------------------------------------------------------------------------
__device__ __forceinline__ unsigned long long pk2(float lo, float hi) {
    unsigned long long r;
    asm("mov.b64 %0, {%1, %2};" : "=l"(r) : "f"(lo), "f"(hi));
    return r;
}
__device__ __forceinline__ void unpk2(float& lo, float& hi, unsigned long long v) {
    asm("mov.b64 {%0, %1}, %2;" : "=f"(lo), "=f"(hi) : "l"(v));
}
__device__ __forceinline__ unsigned long long fma2_(unsigned long long a,
                                                    unsigned long long b,
                                                    unsigned long long c) {
    unsigned long long d;
    asm("fma.rn.f32x2 %0, %1, %2, %3;" : "=l"(d) : "l"(a), "l"(b), "l"(c));
    return d;
}
__device__ __forceinline__ unsigned long long mul2_(unsigned long long a,
                                                    unsigned long long b) {
    unsigned long long d;
    asm("mul.rn.f32x2 %0, %1, %2;" : "=l"(d) : "l"(a), "l"(b));
    return d;
}

__device__ __forceinline__ float sigmoidf_(float x) {
    return 1.f / (1.f + __expf(-x));
}

// ---------------------------------------------------------------------------
// GEMM 1: projections — BM=128, BN=64, BK=16, 8x4 microtile, 256 threads.
// Minimal delta from the measured R3/R9 kernel: M-tile doubled so each kk
// does 32 FMA per 3 LDS.128 (was 16 per 2) — shifts LDS-bound -> FMA-bound.
// ---------------------------------------------------------------------------
#define PBM 128
#define PBN 64
#define PBK 16

__global__ __launch_bounds__(256)
void proj_gemm(const float* __restrict__ X,
               const float* __restrict__ Wq, const float* __restrict__ Wk,
               const float* __restrict__ Wv, const float* __restrict__ Wb,
               const float* __restrict__ Wg, const float* __restrict__ Wp1,
               const float* __restrict__ Wp2, const float* __restrict__ Wp3)
{
    __shared__ float Xs[PBK][PBM + 4];
    __shared__ float Ws[PBK][PBN + 4];

    const int tid = threadIdx.x;
    const int m0 = blockIdx.y * PBM;
    const int n0 = blockIdx.x * PBN;

    // A loader: 128 rows x 16 k = 2048 floats; thread -> row tid>>1,
    // k offset (tid&1)*8, two float4 loads.
    const int alr = tid >> 1;
    const int alc = (tid & 1) * 8;
    // B loader: 64 rows x 16 k = 1024 floats; thread -> row tid>>2,
    // k offset (tid&3)*4, one float4 (same as measured R3 kernel).
    const int blr = tid >> 2;
    const int blc = (tid & 3) * 4;

    // compute roles: 16x16 grid, 8 rows x 4 cols each
    const int tx = tid & 15;
    const int ty = tid >> 4;

    // resolve weight row pointer for global column n0 + blr
    const int n = n0 + blr;
    const float* wrow = nullptr;
    if (n < 2560) {
        const int wi = n >> 9;
        const int nl = n & 511;
        const float* wb = (wi == 0) ? Wq : (wi == 1) ? Wk : (wi == 2) ? Wv
                         : (wi == 3) ? Wb : Wg;
        wrow = wb + nl * DIM_;
    } else if (n < NPROJ) {
        const int nn = n - 2560;
        const int wi = nn >> 5;
        const int nl = nn & 31;
        const float* wb = (wi == 0) ? Wp1 : (wi == 1) ? Wp2 : Wp3;
        wrow = wb + nl * DIM_;
    }
    const float* xrow = X + (size_t)(m0 + alr) * DIM_;

    float acc[8][4];
#pragma unroll
    for (int i = 0; i < 8; i++)
#pragma unroll
        for (int j = 0; j < 4; j++) acc[i][j] = 0.f;

    for (int k0 = 0; k0 < DIM_; k0 += PBK) {
        float4 x0 = *(const float4*)(xrow + k0 + alc);
        float4 x1 = *(const float4*)(xrow + k0 + alc + 4);
        float4 wv = make_float4(0.f, 0.f, 0.f, 0.f);
        if (wrow) wv = *(const float4*)(wrow + k0 + blc);
        Xs[alc + 0][alr] = x0.x; Xs[alc + 1][alr] = x0.y;
        Xs[alc + 2][alr] = x0.z; Xs[alc + 3][alr] = x0.w;
        Xs[alc + 4][alr] = x1.x; Xs[alc + 5][alr] = x1.y;
        Xs[alc + 6][alr] = x1.z; Xs[alc + 7][alr] = x1.w;
        Ws[blc + 0][blr] = wv.x; Ws[blc + 1][blr] = wv.y;
        Ws[blc + 2][blr] = wv.z; Ws[blc + 3][blr] = wv.w;
        __syncthreads();
#pragma unroll
        for (int kk = 0; kk < PBK; kk++) {
            float4 a0 = *(const float4*)&Xs[kk][ty * 8];
            float4 a1 = *(const float4*)&Xs[kk][ty * 8 + 4];
            float4 bq = *(const float4*)&Ws[kk][tx * 4];
            float av[8] = {a0.x, a0.y, a0.z, a0.w, a1.x, a1.y, a1.z, a1.w};
            float bv[4] = {bq.x, bq.y, bq.z, bq.w};
#pragma unroll
            for (int i = 0; i < 8; i++)
#pragma unroll
                for (int j = 0; j < 4; j++)
                    acc[i][j] = fmaf(av[i], bv[j], acc[i][j]);
        }
        __syncthreads();
    }

#pragma unroll
    for (int i = 0; i < 8; i++) {
        const int m = m0 + ty * 8 + i;
        float* dst = g_proj + (size_t)m * NPROJ_PAD + n0 + tx * 4;
        *(float4*)dst = make_float4(acc[i][0], acc[i][1], acc[i][2], acc[i][3]);
    }
}

// ---------------------------------------------------------------------------
// GEMM 2: direct output GEMM with fused bias (R9 measured).
// ---------------------------------------------------------------------------
#define BM 64
#define BN 64
#define BK 16

__global__ __launch_bounds__(256)
void out_gemm(const float* __restrict__ Wo, const float* __restrict__ bo,
              float* __restrict__ out)
{
    __shared__ float Xs[BK][BM + 4];
    __shared__ float Ws[BK][BN + 4];

    const int tid = threadIdx.x;
    const int m0 = blockIdx.y * BM;
    const int n0 = blockIdx.x * BN;

    const int lr = tid >> 2;
    const int lc = (tid & 3) * 4;
    const int tx = tid & 15;
    const int ty = tid >> 4;

    const float* xrow = g_attn + (size_t)(m0 + lr) * DIM_;
    const float* wrow = Wo + (size_t)(n0 + lr) * DIM_;

    float acc[4][4];
#pragma unroll
    for (int i = 0; i < 4; i++)
#pragma unroll
        for (int j = 0; j < 4; j++) acc[i][j] = 0.f;

    for (int k0 = 0; k0 < DIM_; k0 += BK) {
        float4 xv = *(const float4*)(xrow + k0 + lc);
        float4 wv = *(const float4*)(wrow + k0 + lc);
        Xs[lc + 0][lr] = xv.x; Xs[lc + 1][lr] = xv.y;
        Xs[lc + 2][lr] = xv.z; Xs[lc + 3][lr] = xv.w;
        Ws[lc + 0][lr] = wv.x; Ws[lc + 1][lr] = wv.y;
        Ws[lc + 2][lr] = wv.z; Ws[lc + 3][lr] = wv.w;
        __syncthreads();
#pragma unroll
        for (int kk = 0; kk < BK; kk++) {
            float4 a = *(const float4*)&Xs[kk][ty * 4];
            float4 bq = *(const float4*)&Ws[kk][tx * 4];
            float av[4] = {a.x, a.y, a.z, a.w};
            float bv[4] = {bq.x, bq.y, bq.z, bq.w};
#pragma unroll
            for (int i = 0; i < 4; i++)
#pragma unroll
                for (int j = 0; j < 4; j++)
                    acc[i][j] = fmaf(av[i], bv[j], acc[i][j]);
        }
        __syncthreads();
    }

#pragma unroll
    for (int i = 0; i < 4; i++) {
        const int m = m0 + ty * 4 + i;
#pragma unroll
        for (int j = 0; j < 4; j++) {
            const int nn = n0 + tx * 4 + j;
            out[(size_t)m * DIM_ + nn] = acc[i][j] + bo[nn];
        }
    }
}

// ---------------------------------------------------------------------------
// Scan kernel (R9 measured): 2 blocks per (b,h) (d-split), CHUNK-2.
// ---------------------------------------------------------------------------
__global__ __launch_bounds__(256)
void scan_kernel(const int* __restrict__ term,
                 const float* __restrict__ kv_prev,
                 const float* __restrict__ nm_prev,
                 float* __restrict__ kv_out,
                 float* __restrict__ nm_out)
{
    const int blk = blockIdx.x;      // 0..255
    const int bh  = blk >> 1;
    const int ds  = blk & 1;
    const int b   = bh >> 3;
    const int h   = bh & 7;
    const int tid = threadIdx.x;
    const int fg  = tid >> 5;        // FD group (32 rows)
    const int dl  = tid & 31;
    const int d   = ds * 32 + dl;
    const int ED  = tid;
    const int e   = ED >> 6;
    const int dd  = ED & 63;

    __shared__ float s_disc[2][FD_];
    __shared__ float s_gk[2][FD_];
    __shared__ float s_phi[2][FD_];
    __shared__ float s_gv[2][32];
    __shared__ float s_numred[2][8][32];
    __shared__ float s_denred[2][2][8];   // [parity][step][fg]

    unsigned long long kv2[16];
    {
        const float* kvp = kv_prev + (size_t)bh * FD_ * DH_;
#pragma unroll
        for (int p = 0; p < 16; p++) {
            const float lo = kvp[(fg * 32 + 2*p    ) * DH_ + d];
            const float hi = kvp[(fg * 32 + 2*p + 1) * DH_ + d];
            kv2[p] = pk2(lo, hi);
        }
    }
    float nm = nm_prev[bh * FD_ + ED];

    const int hcol = h * DH_;
    const int pofs = h * ETA_ + e;

    float rq[2], rk[2], rg[2], rp1[2], rp2[2], rp3[2], rv[2], rb[2];
    int rtm[2];

#pragma unroll
    for (int i = 0; i < 2; i++) {
        const float* P = g_proj + (size_t)(i * B_ + b) * NPROJ_PAD;
        rq[i]  = P[hcol + dd];
        rk[i]  = P[512 + hcol + dd];
        rg[i]  = P[2048 + hcol + dd];
        rp1[i] = P[2560 + pofs];
        rp2[i] = P[2592 + pofs];
        rp3[i] = P[2624 + pofs];
        rtm[i] = term[i * B_ + b];
        if (tid < 32) {
            rv[i] = P[1024 + hcol + ds * 32 + tid];
            rb[i] = P[1536 + hcol + ds * 32 + tid];
        }
    }

    for (int c = 0; c < 32; c++) {
        const int par = c & 1;

        float den[2];
#pragma unroll
        for (int i = 0; i < 2; i++) {
            const float sgamma = sigmoidf_(rg[i]);
            const float gf   = sigmoidf_(rp3[i]) * sgamma;
            const float mask = rtm[i] ? 0.f : 1.f;
            const float disc = (1.f - gf) * mask;
            const float gkv  = fmaxf(rp1[i], 0.f) * rk[i] * gf;
            const float phi  = fmaxf(rp2[i], 0.f) * rq[i];
            s_disc[i][ED] = disc;
            s_gk[i][ED]   = gkv;
            s_phi[i][ED]  = phi;
            nm = fmaf(disc, nm, gkv);
            den[i] = phi * nm;
        }
        if (tid < 32) {
#pragma unroll
            for (int i = 0; i < 2; i++)
                s_gv[i][tid] = rv[i] * sigmoidf_(rb[i]);
        }

#pragma unroll
        for (int o = 16; o; o >>= 1) {
            den[0] += __shfl_xor_sync(0xFFFFFFFFu, den[0], o);
            den[1] += __shfl_xor_sync(0xFFFFFFFFu, den[1], o);
        }
        if (dl == 0) {
            s_denred[par][0][fg] = den[0];
            s_denred[par][1][fg] = den[1];
        }

        if (c < 31) {
#pragma unroll
            for (int i = 0; i < 2; i++) {
                const int tt = (c + 1) * 2 + i;
                const float* Pn = g_proj + (size_t)(tt * B_ + b) * NPROJ_PAD;
                rq[i]  = Pn[hcol + dd];
                rk[i]  = Pn[512 + hcol + dd];
                rg[i]  = Pn[2048 + hcol + dd];
                rp1[i] = Pn[2560 + pofs];
                rp2[i] = Pn[2592 + pofs];
                rp3[i] = Pn[2624 + pofs];
                rtm[i] = term[tt * B_ + b];
                if (tid < 32) {
                    rv[i] = Pn[1024 + hcol + ds * 32 + tid];
                    rb[i] = Pn[1536 + hcol + ds * 32 + tid];
                }
            }
        }

        __syncthreads();

#pragma unroll
        for (int i = 0; i < 2; i++) {
            const unsigned long long gvd2 = pk2(s_gv[i][dl], s_gv[i][dl]);
            const ulonglong2* dsc2 = (const ulonglong2*)&s_disc[i][fg * 32];
            const ulonglong2* gks2 = (const ulonglong2*)&s_gk[i][fg * 32];
            const ulonglong2* phs2 = (const ulonglong2*)&s_phi[i][fg * 32];
            unsigned long long np01 = 0ULL, np23 = 0ULL;
#pragma unroll
            for (int jq = 0; jq < 8; jq++) {
                const ulonglong2 D = dsc2[jq];
                const ulonglong2 G = gks2[jq];
                const ulonglong2 Ph = phs2[jq];
                kv2[2*jq]     = fma2_(D.x, kv2[2*jq],     mul2_(gvd2, G.x));
                kv2[2*jq + 1] = fma2_(D.y, kv2[2*jq + 1], mul2_(gvd2, G.y));
                np01 = fma2_(kv2[2*jq],     Ph.x, np01);
                np23 = fma2_(kv2[2*jq + 1], Ph.y, np23);
            }
            float a0, a1, a2, a3;
            unpk2(a0, a1, np01);
            unpk2(a2, a3, np23);
            s_numred[i][fg][dl] = (a0 + a1) + (a2 + a3);
        }
        __syncthreads();

        if (tid < 64) {
            const int tt = tid >> 5;
            const int l  = tid & 31;
            float num = 0.f;
#pragma unroll
            for (int g = 0; g < 8; g++) num += s_numred[tt][g][l];
            float dden = 0.f;
#pragma unroll
            for (int g = 0; g < 8; g++) dden += s_denred[par][tt][g];
            const int row = (c * 2 + tt) * B_ + b;
            g_attn[(size_t)row * (H_*DH_) + hcol + ds * 32 + l]
                = num / (dden + 1e-6f);
        }
    }

    float* kvo = kv_out + (size_t)bh * FD_ * DH_;
#pragma unroll
    for (int p = 0; p < 16; p++) {
        float lo, hi;
        unpk2(lo, hi, kv2[p]);
        kvo[(fg * 32 + 2*p    ) * DH_ + d] = lo;
        kvo[(fg * 32 + 2*p + 1) * DH_ + d] = hi;
    }
    if (ds == 0) nm_out[bh * FD_ + ED] = nm;
}

// ---------------------------------------------------------------------------
// Launch
// ---------------------------------------------------------------------------
extern "C" void kernel_launch(void* const* d_in, const int* in_sizes, int n_in,
                              void* d_out, int out_size)
{
    const float* X    = (const float*)d_in[0];
    const int*   term = (const int*)d_in[1];
    const float* kvp  = (const float*)d_in[2];
    const float* nmp  = (const float*)d_in[3];
    const float* Wq   = (const float*)d_in[4];
    const float* Wk   = (const float*)d_in[5];
    const float* Wv   = (const float*)d_in[6];
    const float* Wb   = (const float*)d_in[7];
    const float* Wg   = (const float*)d_in[8];
    const float* Wp1  = (const float*)d_in[9];
    const float* Wp2  = (const float*)d_in[10];
    const float* Wp3  = (const float*)d_in[11];
    const float* Wo   = (const float*)d_in[12];
    const float* bo   = (const float*)d_in[13];
    float* out = (float*)d_out;

    dim3 gp(NPROJ_PAD / PBN, MROWS / PBM);     // 42 x 8 = 336 blocks
    proj_gemm<<<gp, 256>>>(X, Wq, Wk, Wv, Wb, Wg, Wp1, Wp2, Wp3);

    scan_kernel<<<B_ * H_ * 2, 256>>>(term, kvp, nmp,
                                      out + OUT_OFF_KV, out + OUT_OFF_NM);

    dim3 go(DIM_ / BN, MROWS / BM);            // 8 x 16 = 128 blocks
    out_gemm<<<go, 256>>>(Wo, bo, out);
}